// round 3
// baseline (speedup 1.0000x reference)
#include <cuda_runtime.h>

#define BB 128
#define TT 256
#define II 64
#define HH 1024
#define OO 64
#define NCTA 148
#define KC 16
#define NSA 18
#define NSC 16

typedef unsigned long long ull;

// ---------------- persistent device globals (no allocation) ----------------
__device__ float WAt[1088 * HH];          // [k][j]  k<64: Wih1, else Whh1
__device__ float WBt[2048 * HH];          // [k][j]  k<1024: Wih2, else Whh2
__device__ float WGt[2048 * HH];          // [k][j]  Wg
__device__ float WOt[HH * 128];           // [k][o]  o<64: Wo1, else Wo2
__device__ float g_xt[TT * II * BB];      // x transposed [t*I + i][b]
__device__ float g_h1[HH * BB];
__device__ float g_h2[HH * BB];
__device__ float g_u[HH * BB];
__device__ float partMain[NSA * HH * BB]; // [slice][j][b]
__device__ float partHead[NSC * 128 * BB];
__device__ unsigned g_bar;

// ---------------------------------------------------------------------------
__global__ void k_init() {
    int i = blockIdx.x * blockDim.x + threadIdx.x;
    if (i == 0) g_bar = 0u;
    if (i < HH * BB) {
        g_h1[i] = 0.f;
        g_h2[i] = 0.f;
        g_u[i]  = 1.f;
    }
}

__global__ void k_transpose_x(const float* __restrict__ x) {
    __shared__ float tile[32][33];
    int n0 = blockIdx.x * 32;
    int m0 = blockIdx.y * 32;
    int tx = threadIdx.x, ty = threadIdx.y;
    tile[ty][tx] = x[(m0 + ty) * (TT * II) + n0 + tx];
    __syncthreads();
    g_xt[(n0 + ty) * BB + m0 + tx] = tile[tx][ty];
}

__global__ void k_prep(const float* __restrict__ Wih1, const float* __restrict__ Whh1,
                       const float* __restrict__ Wih2, const float* __restrict__ Whh2,
                       const float* __restrict__ Wg,
                       const float* __restrict__ Wo1, const float* __restrict__ Wo2)
{
    int stride = gridDim.x * blockDim.x;
    int t0 = blockIdx.x * blockDim.x + threadIdx.x;
    for (int i = t0; i < 1088 * HH; i += stride) {
        int k = i / HH, j = i % HH;
        WAt[i] = (k < II) ? Wih1[j * II + k] : Whh1[(size_t)j * HH + (k - II)];
    }
    for (int i = t0; i < 2048 * HH; i += stride) {
        int k = i / HH, j = i % HH;
        WBt[i] = (k < HH) ? Wih2[(size_t)j * HH + k]
                          : Whh2[(size_t)j * HH + (k - HH)];
        WGt[i] = Wg[(size_t)j * 2048 + k];
    }
    for (int i = t0; i < HH * 128; i += stride) {
        int k = i >> 7, o = i & 127;
        WOt[i] = (o < 64) ? Wo1[o * HH + k] : Wo2[(o - 64) * HH + k];
    }
}

// ---------------------------------------------------------------------------
__device__ __forceinline__ void gsync(unsigned &target) {
    __syncthreads();
    target += NCTA;
    if (threadIdx.x == 0) {
        __threadfence();
        atomicAdd(&g_bar, 1u);
        while (*(volatile unsigned*)&g_bar < target) { }
    }
    __syncthreads();
    __threadfence();   // acquire: CCTL.IVALL so stale L1 lines are dropped
}

// ---------------------------------------------------------------------------
// GEMM work unit: C[128 j][128 b] over chunks [c0,c1) of KC=16 k each.
// 512 threads; thread (tx=lane, ty=warp): 4 batches (tx*4) x 8 outputs (ty*8).
// f32x2 packed over j-pairs; act value splatted in registers.
// Head mode (actH != null): warps ty>=8 consume actH instead of actA.
__device__ __forceinline__ void gemm_unit(
    const float* __restrict__ actA, int splitK, const float* __restrict__ actB,
    const float* __restrict__ actH,
    const float* __restrict__ Wt, int ldw,
    int j0, int c0, int c1, float* __restrict__ dst,
    float (*sAct)[2][KC][BB], float (*sW)[KC][128], int tid)
{
    const int tx = tid & 31, ty = tid >> 5;
    const int lkk = tid >> 5, lb4 = (tid & 31) * 4;
    const int sel = (actH && ty >= 8) ? 1 : 0;

    ull acc[4][4];
    #pragma unroll
    for (int b4 = 0; b4 < 4; b4++)
        #pragma unroll
        for (int jp = 0; jp < 4; jp++) acc[b4][jp] = 0ull;

    float4 ra, rh, rw;
    // prologue load chunk c0
    {
        int k = c0 * KC + lkk;
        const float* s = (k < splitK) ? (actA + (size_t)k * BB)
                                      : (actB + (size_t)(k - splitK) * BB);
        ra = *reinterpret_cast<const float4*>(s + lb4);
        if (actH) rh = *reinterpret_cast<const float4*>(actH + (size_t)k * BB + lb4);
        rw = *reinterpret_cast<const float4*>(Wt + (size_t)k * ldw + j0 + lb4);
    }
    *reinterpret_cast<float4*>(&sAct[0][0][lkk][lb4]) = ra;
    if (actH) *reinterpret_cast<float4*>(&sAct[1][0][lkk][lb4]) = rh;
    *reinterpret_cast<float4*>(&sW[0][lkk][lb4]) = rw;
    __syncthreads();

    int buf = 0;
    for (int c = c0; c < c1; c++) {
        bool more = (c + 1 < c1);
        if (more) {
            int k = (c + 1) * KC + lkk;
            const float* s = (k < splitK) ? (actA + (size_t)k * BB)
                                          : (actB + (size_t)(k - splitK) * BB);
            ra = *reinterpret_cast<const float4*>(s + lb4);
            if (actH) rh = *reinterpret_cast<const float4*>(actH + (size_t)k * BB + lb4);
            rw = *reinterpret_cast<const float4*>(Wt + (size_t)k * ldw + j0 + lb4);
        }
        #pragma unroll
        for (int kk = 0; kk < KC; kk++) {
            float4 a4 = *reinterpret_cast<const float4*>(&sAct[sel][buf][kk][tx * 4]);
            ull xs[4];
            asm("mov.b64 %0, {%1, %1};" : "=l"(xs[0]) : "r"(__float_as_uint(a4.x)));
            asm("mov.b64 %0, {%1, %1};" : "=l"(xs[1]) : "r"(__float_as_uint(a4.y)));
            asm("mov.b64 %0, {%1, %1};" : "=l"(xs[2]) : "r"(__float_as_uint(a4.z)));
            asm("mov.b64 %0, {%1, %1};" : "=l"(xs[3]) : "r"(__float_as_uint(a4.w)));
            ulonglong2 w01 = *reinterpret_cast<const ulonglong2*>(&sW[buf][kk][ty * 8]);
            ulonglong2 w23 = *reinterpret_cast<const ulonglong2*>(&sW[buf][kk][ty * 8 + 4]);
            ull wv[4] = {w01.x, w01.y, w23.x, w23.y};
            #pragma unroll
            for (int b4 = 0; b4 < 4; b4++)
                #pragma unroll
                for (int jp = 0; jp < 4; jp++)
                    asm("fma.rn.f32x2 %0, %1, %2, %0;"
                        : "+l"(acc[b4][jp]) : "l"(wv[jp]), "l"(xs[b4]));
        }
        if (more) {
            *reinterpret_cast<float4*>(&sAct[0][buf ^ 1][lkk][lb4]) = ra;
            if (actH) *reinterpret_cast<float4*>(&sAct[1][buf ^ 1][lkk][lb4]) = rh;
            *reinterpret_cast<float4*>(&sW[buf ^ 1][lkk][lb4]) = rw;
        }
        __syncthreads();
        buf ^= 1;
    }

    // writeout: regather lo/hi across the 4 batches -> coalesced STG.128
    #pragma unroll
    for (int jp = 0; jp < 4; jp++) {
        float2 p0 = *reinterpret_cast<float2*>(&acc[0][jp]);
        float2 p1 = *reinterpret_cast<float2*>(&acc[1][jp]);
        float2 p2 = *reinterpret_cast<float2*>(&acc[2][jp]);
        float2 p3 = *reinterpret_cast<float2*>(&acc[3][jp]);
        int j = ty * 8 + 2 * jp;
        *reinterpret_cast<float4*>(dst + (size_t)j * BB + tx * 4)
            = make_float4(p0.x, p1.x, p2.x, p3.x);
        *reinterpret_cast<float4*>(dst + (size_t)(j + 1) * BB + tx * 4)
            = make_float4(p0.y, p1.y, p2.y, p3.y);
    }
}

// ---------------------------------------------------------------------------
__global__ void __launch_bounds__(512, 1) k_rnn(
    const float* __restrict__ bih1, const float* __restrict__ bhh1,
    const float* __restrict__ bih2, const float* __restrict__ bhh2,
    const float* __restrict__ bg,
    const float* __restrict__ bo1, const float* __restrict__ bo2,
    float* __restrict__ out)
{
    __shared__ float sAct[2][2][KC][BB];   // [sel][buf][kk][b]  32 KB
    __shared__ float sW[2][KC][128];       // [buf][kk][j]       16 KB
    const int tid = threadIdx.x;
    const int u = blockIdx.x;
    unsigned target = 0;
    const int n4 = HH * BB / 4;

    for (int t = 0; t < TT; t++) {
        // ---- phase A: preact h1 = x_t@Wih1^T + h1@Whh1^T (K=1088) ----
        if (u < 144) {
            int jt = u & 7, ks = u >> 3;
            gemm_unit(g_xt + (size_t)t * II * BB, II, g_h1, nullptr,
                      WAt, HH, jt * 128,
                      (ks * 68) / NSA, ((ks + 1) * 68) / NSA,
                      partMain + (size_t)ks * (HH * BB) + (size_t)jt * 128 * BB,
                      sAct, sW, tid);
        }
        gsync(target);
        // ---- reduce A ----
        for (int i4 = u * 512 + tid; i4 < n4; i4 += NCTA * 512) {
            int j = (i4 * 4) >> 7;
            float b0 = bih1[j] + bhh1[j];
            float4 s = make_float4(b0, b0, b0, b0);
            #pragma unroll
            for (int ss = 0; ss < NSA; ss++) {
                float4 p = reinterpret_cast<const float4*>(partMain)[ss * n4 + i4];
                s.x += p.x; s.y += p.y; s.z += p.z; s.w += p.w;
            }
            reinterpret_cast<float4*>(g_h1)[i4] =
                make_float4(tanhf(s.x), tanhf(s.y), tanhf(s.z), tanhf(s.w));
        }
        gsync(target);
        // ---- phase B: preact h2cand (K=2048: h1|h2) ----
        if (u < 144) {
            int jt = u & 7, ks = u >> 3;
            gemm_unit(g_h1, HH, g_h2, nullptr, WBt, HH, jt * 128,
                      (ks * 128) / NSA, ((ks + 1) * 128) / NSA,
                      partMain + (size_t)ks * (HH * BB) + (size_t)jt * 128 * BB,
                      sAct, sW, tid);
        }
        gsync(target);
        // ---- reduce B: h2 = u*tanh(.) + (1-u)*h2 ----
        for (int i4 = u * 512 + tid; i4 < n4; i4 += NCTA * 512) {
            int j = (i4 * 4) >> 7;
            float b0 = bih2[j] + bhh2[j];
            float4 s = make_float4(b0, b0, b0, b0);
            #pragma unroll
            for (int ss = 0; ss < NSA; ss++) {
                float4 p = reinterpret_cast<const float4*>(partMain)[ss * n4 + i4];
                s.x += p.x; s.y += p.y; s.z += p.z; s.w += p.w;
            }
            float4 uu = reinterpret_cast<const float4*>(g_u)[i4];
            float4 hp = reinterpret_cast<const float4*>(g_h2)[i4];
            float4 r;
            r.x = uu.x * tanhf(s.x) + (1.f - uu.x) * hp.x;
            r.y = uu.y * tanhf(s.y) + (1.f - uu.y) * hp.y;
            r.z = uu.z * tanhf(s.z) + (1.f - uu.z) * hp.z;
            r.w = uu.w * tanhf(s.w) + (1.f - uu.w) * hp.w;
            reinterpret_cast<float4*>(g_h2)[i4] = r;
        }
        gsync(target);
        // ---- phase C: gate (128 CTAs) + output heads (16 CTAs) ----
        if (u < 128) {
            int jt = u & 7, ks = u >> 3;   // ks 0..15, 8 chunks each
            gemm_unit(g_h1, HH, g_h2, nullptr, WGt, HH, jt * 128,
                      ks * 8, ks * 8 + 8,
                      partMain + (size_t)ks * (HH * BB) + (size_t)jt * 128 * BB,
                      sAct, sW, tid);
        } else if (u < 144) {
            int ks = u - 128;              // 0..15, 4 chunks of K=1024
            gemm_unit(g_h1, 1 << 30, g_h1, g_h2, WOt, 128, 0,
                      ks * 4, ks * 4 + 4,
                      partHead + (size_t)ks * (128 * BB),
                      sAct, sW, tid);
        }
        gsync(target);
        // ---- reduce C: u = sigmoid(.), out = tanh+tanh ----
        for (int i4 = u * 512 + tid; i4 < n4; i4 += NCTA * 512) {
            int j = (i4 * 4) >> 7;
            float b0 = bg[j];
            float4 s = make_float4(b0, b0, b0, b0);
            #pragma unroll
            for (int ss = 0; ss < NSC; ss++) {
                float4 p = reinterpret_cast<const float4*>(partMain)[ss * n4 + i4];
                s.x += p.x; s.y += p.y; s.z += p.z; s.w += p.w;
            }
            float4 r;
            r.x = 1.f / (1.f + expf(-s.x));
            r.y = 1.f / (1.f + expf(-s.y));
            r.z = 1.f / (1.f + expf(-s.z));
            r.w = 1.f / (1.f + expf(-s.w));
            reinterpret_cast<float4*>(g_u)[i4] = r;
        }
        for (int i = u * 512 + tid; i < OO * BB; i += NCTA * 512) {
            int o = i >> 7, b = i & 127;
            float s1 = bo1[o], s2 = bo2[o];
            #pragma unroll
            for (int ss = 0; ss < NSC; ss++) {
                s1 += partHead[ss * (128 * BB) + o * BB + b];
                s2 += partHead[ss * (128 * BB) + (o + 64) * BB + b];
            }
            out[((size_t)b * TT + t) * OO + o] = tanhf(s1) + tanhf(s2);
        }
        gsync(target);
    }
}

// ---------------------------------------------------------------------------
extern "C" void kernel_launch(void* const* d_in, const int* in_sizes, int n_in,
                              void* d_out, int out_size) {
    const float* x    = (const float*)d_in[0];
    const float* Wih1 = (const float*)d_in[1];
    const float* bih1 = (const float*)d_in[2];
    const float* Whh1 = (const float*)d_in[3];
    const float* bhh1 = (const float*)d_in[4];
    const float* Wih2 = (const float*)d_in[5];
    const float* bih2 = (const float*)d_in[6];
    const float* Whh2 = (const float*)d_in[7];
    const float* bhh2 = (const float*)d_in[8];
    const float* Wg   = (const float*)d_in[9];
    const float* bg   = (const float*)d_in[10];
    const float* Wo1  = (const float*)d_in[11];
    const float* bo1  = (const float*)d_in[12];
    const float* Wo2  = (const float*)d_in[13];
    const float* bo2  = (const float*)d_in[14];
    float* out = (float*)d_out;

    k_init<<<(HH * BB + 255) / 256, 256>>>();
    k_transpose_x<<<dim3(TT * II / 32, BB / 32), dim3(32, 32)>>>(x);
    k_prep<<<512, 256>>>(Wih1, Whh1, Wih2, Whh2, Wg, Wo1, Wo2);
    k_rnn<<<NCTA, 512>>>(bih1, bhh1, bih2, bhh2, bg, bo1, bo2, out);
}

// round 6
// speedup vs baseline: 1.6924x; 1.6924x over previous
#include <cuda_runtime.h>
#include <cstdint>

#define BB 128
#define TT 256
#define II 64
#define HH 1024
#define OO 64
#define NCTA 148

#if defined(__CUDA_ARCH_FEAT_SM103_ALL) || defined(__CUDA_ARCH_SPECIFIC__)
#define HAS_TCGEN05 1
#else
#define HAS_TCGEN05 0
#endif

// idesc: dtype=F32(1<<4), atype=TF32(2<<7), btype=TF32(2<<10), N/8=8<<17, M/16=8<<24
#define IDESC_TF32 0x8100910u

// smem layout (dynamic):
// [0]=tmem ptr, [8]=mbar
// A_hi @1024 (64KB), A_lo @66560 (64KB), B_hi @132096 (32KB), B_lo @164864 (32KB)
#define SM_AHI 1024
#define SM_ALO 66560
#define SM_BHI 132096
#define SM_BLO 164864
#define SMEM_BYTES 197632

// ---------------- persistent device globals ----------------
__device__ float bufX[TT * BB * II];   // x as [t][b][i]
__device__ float bufH1[BB * HH];       // h1 [b][j]
__device__ float bufH2[BB * HH];       // h2 [b][j]
__device__ float g_u[BB * HH];         // gate [b][j]
__device__ float partA[9 * BB * HH];   // split-K partials [s][b][j]
__device__ float partH[4 * BB * 128];  // head partials [s][b][o(128)]
__device__ unsigned g_bar;

// ---------------------------------------------------------------------------
__global__ void k_init() {
    int i = blockIdx.x * blockDim.x + threadIdx.x;
    if (i == 0) g_bar = 0u;
    if (i < BB * HH) { bufH1[i] = 0.f; bufH2[i] = 0.f; g_u[i] = 1.f; }
}

__global__ void k_prepx(const float* __restrict__ x) {
    int idx = blockIdx.x * blockDim.x + threadIdx.x;
    if (idx < TT * BB * II) {
        int t = idx / (BB * II);
        int r = idx - t * (BB * II);
        int b = r >> 6, i = r & 63;
        bufX[idx] = x[((size_t)b * TT + t) * II + i];
    }
}

// ---------------------------------------------------------------------------
__device__ __forceinline__ uint32_t cvta_s(const void* p) {
    uint32_t a;
    asm("{ .reg .u64 t; cvta.to.shared.u64 t, %1; cvt.u32.u64 %0, t; }"
        : "=r"(a) : "l"(p));
    return a;
}

__device__ __forceinline__ bool elect1() {
    uint32_t p;
    asm volatile("{ .reg .pred p; elect.sync _|p, 0xFFFFFFFF; selp.b32 %0, 1, 0, p; }"
                 : "=r"(p));
    return p != 0;
}

__device__ __forceinline__ uint64_t sdesc(uint32_t addr) {
    // SW128 (2<<61) | version(1<<46) | SBO=64<<32 | LBO=1<<16
    return 0x4000404000010000ull | ((uint64_t)(addr >> 4) & 0x3FFF);
}

__device__ __forceinline__ void mbar_wait(uint32_t mbar, uint32_t parity) {
    asm volatile(
        "{\n\t.reg .pred P;\n\t"
        "WL%=:\n\t"
        "mbarrier.try_wait.parity.acquire.cta.shared::cta.b64 P, [%0], %1, 0x989680;\n\t"
        "@!P bra WL%=;\n\t}"
        :: "r"(mbar), "r"(parity) : "memory");
}

__device__ __forceinline__ void gsync(unsigned &target) {
    __syncthreads();
    target += NCTA;
    if (threadIdx.x == 0) {
        __threadfence();
        atomicAdd(&g_bar, 1u);
        while (*(volatile unsigned*)&g_bar < target) { }
    }
    __syncthreads();
    __threadfence();   // acquire: drop stale L1 lines
}

// exact hi/lo split: hi = tf32-truncation of x (low 13 mantissa bits zero),
// lo = x - hi (exact in fp32)
__device__ __forceinline__ void split_f4(float4 v, float4 &hi, float4 &lo) {
    hi.x = __uint_as_float(__float_as_uint(v.x) & 0xFFFFE000u); lo.x = v.x - hi.x;
    hi.y = __uint_as_float(__float_as_uint(v.y) & 0xFFFFE000u); lo.y = v.y - hi.y;
    hi.z = __uint_as_float(__float_as_uint(v.z) & 0xFFFFE000u); lo.z = v.z - hi.z;
    hi.w = __uint_as_float(__float_as_uint(v.w) & 0xFFFFE000u); lo.w = v.w - hi.w;
}

#if HAS_TCGEN05
#define LDTM32(r, a) \
    asm volatile( \
        "tcgen05.ld.sync.aligned.32x32b.x32.b32 " \
        "{%0, %1, %2, %3, %4, %5, %6, %7, " \
        " %8, %9, %10, %11, %12, %13, %14, %15, " \
        " %16, %17, %18, %19, %20, %21, %22, %23, " \
        " %24, %25, %26, %27, %28, %29, %30, %31}, [%32];" \
        : "=r"((r)[0]),  "=r"((r)[1]),  "=r"((r)[2]),  "=r"((r)[3]), \
          "=r"((r)[4]),  "=r"((r)[5]),  "=r"((r)[6]),  "=r"((r)[7]), \
          "=r"((r)[8]),  "=r"((r)[9]),  "=r"((r)[10]), "=r"((r)[11]), \
          "=r"((r)[12]), "=r"((r)[13]), "=r"((r)[14]), "=r"((r)[15]), \
          "=r"((r)[16]), "=r"((r)[17]), "=r"((r)[18]), "=r"((r)[19]), \
          "=r"((r)[20]), "=r"((r)[21]), "=r"((r)[22]), "=r"((r)[23]), \
          "=r"((r)[24]), "=r"((r)[25]), "=r"((r)[26]), "=r"((r)[27]), \
          "=r"((r)[28]), "=r"((r)[29]), "=r"((r)[30]), "=r"((r)[31]) \
        : "r"(a))

__device__ __forceinline__ void mma_tf32(uint32_t tmem, uint64_t a, uint64_t b,
                                         uint32_t en) {
    asm volatile(
        "{\n\t.reg .pred p;\n\t"
        "setp.ne.u32 p, %4, 0;\n\t"
        "tcgen05.mma.cta_group::1.kind::tf32 [%0], %1, %2, %3, "
        "{%5, %5, %5, %5}, p;\n\t}"
        :: "r"(tmem), "l"(a), "l"(b), "r"(IDESC_TF32), "r"(en), "r"(0u)
        : "memory");
}
#endif

// ---------------------------------------------------------------------------
// One split-K work unit: D[b=128][64 j] = A[128 x K] @ B[64 x K]^T in 3xTF32.
// Loops chunks of <=128 k. Fallback (base-arch pass only): exact SIMT FMA.
__device__ __forceinline__ void run_unit(
    const float* __restrict__ Asrc, int lda,
    const float* __restrict__ Bsrc, int ldb,
    int K, uint32_t sb, float* __restrict__ smf, uint32_t tmem,
    float* __restrict__ dst, int ldd,
    int tid, uint32_t &mctr)
{
#if HAS_TCGEN05
    const uint32_t smM = sb + 8;
    for (int c0 = 0; c0 < K; c0 += 128) {
        const int kch = (K - c0 < 128) ? (K - c0) : 128;
        const int K4 = kch >> 2;
        const int k4sh = (kch == 64) ? 4 : 5;

        // ---- load + split A tile: 128 rows (16 atom-rows) ----
        for (int i = tid; i < 128 * K4; i += 128) {
            int r = i >> k4sh, c4 = i & (K4 - 1);
            float4 v = *reinterpret_cast<const float4*>(
                Asrc + (size_t)r * lda + c0 + c4 * 4);
            float4 hi, lo;
            split_f4(v, hi, lo);
            int bo = (((c4 >> 3) * 16 + (r >> 3)) << 10) | ((r & 7) << 7) | ((c4 & 7) << 4);
            uint32_t sw = bo ^ ((bo >> 3) & 0x70);
            asm volatile("st.shared.v4.b32 [%0], {%1,%2,%3,%4};"
                :: "r"(sb + SM_AHI + sw), "r"(__float_as_uint(hi.x)),
                   "r"(__float_as_uint(hi.y)), "r"(__float_as_uint(hi.z)),
                   "r"(__float_as_uint(hi.w)) : "memory");
            asm volatile("st.shared.v4.b32 [%0], {%1,%2,%3,%4};"
                :: "r"(sb + SM_ALO + sw), "r"(__float_as_uint(lo.x)),
                   "r"(__float_as_uint(lo.y)), "r"(__float_as_uint(lo.z)),
                   "r"(__float_as_uint(lo.w)) : "memory");
        }
        // ---- load + split B tile: 64 rows (8 atom-rows) ----
        for (int i = tid; i < 64 * K4; i += 128) {
            int r = i >> k4sh, c4 = i & (K4 - 1);
            float4 v = *reinterpret_cast<const float4*>(
                Bsrc + (size_t)r * ldb + c0 + c4 * 4);
            float4 hi, lo;
            split_f4(v, hi, lo);
            int bo = (((c4 >> 3) * 8 + (r >> 3)) << 10) | ((r & 7) << 7) | ((c4 & 7) << 4);
            uint32_t sw = bo ^ ((bo >> 3) & 0x70);
            asm volatile("st.shared.v4.b32 [%0], {%1,%2,%3,%4};"
                :: "r"(sb + SM_BHI + sw), "r"(__float_as_uint(hi.x)),
                   "r"(__float_as_uint(hi.y)), "r"(__float_as_uint(hi.z)),
                   "r"(__float_as_uint(hi.w)) : "memory");
            asm volatile("st.shared.v4.b32 [%0], {%1,%2,%3,%4};"
                :: "r"(sb + SM_BLO + sw), "r"(__float_as_uint(lo.x)),
                   "r"(__float_as_uint(lo.y)), "r"(__float_as_uint(lo.z)),
                   "r"(__float_as_uint(lo.w)) : "memory");
        }
        asm volatile("fence.proxy.async.shared::cta;" ::: "memory");
        __syncthreads();

        if (tid < 32 && elect1()) {
            uint64_t ahi = sdesc(sb + SM_AHI), alo = sdesc(sb + SM_ALO);
            uint64_t bhi = sdesc(sb + SM_BHI), blo = sdesc(sb + SM_BLO);
            int steps = kch >> 3;                 // tf32: K=8 per mma
            for (int s = 0; s < steps; s++) {
                uint64_t oa = (uint64_t)(((s >> 2) << 10) + ((s & 3) << 1));
                uint64_t ob = (uint64_t)(((s >> 2) << 9) + ((s & 3) << 1));
                uint32_t en0 = (c0 > 0 || s > 0) ? 1u : 0u;
                mma_tf32(tmem, ahi + oa, bhi + ob, en0);   // hi*hi
                mma_tf32(tmem, ahi + oa, blo + ob, 1u);    // hi*lo
                mma_tf32(tmem, alo + oa, bhi + ob, 1u);    // lo*hi
            }
            asm volatile(
                "tcgen05.commit.cta_group::1.mbarrier::arrive::one.shared::cluster.b64 [%0];"
                :: "r"(smM) : "memory");
        }
        mbar_wait(smM, mctr & 1);
        mctr++;
    }
    asm volatile("tcgen05.fence::after_thread_sync;" ::: "memory");

    uint32_t d0[32], d1[32];
    LDTM32(d0, tmem);
    LDTM32(d1, tmem + 32);
    asm volatile("tcgen05.wait::ld.sync.aligned;" ::: "memory");
    asm volatile("tcgen05.fence::before_thread_sync;" ::: "memory");

    float* drow = dst + (size_t)tid * ldd;       // row b == tid
    #pragma unroll
    for (int c4 = 0; c4 < 8; c4++) {
        *reinterpret_cast<float4*>(drow + c4 * 4) = make_float4(
            __uint_as_float(d0[c4 * 4 + 0]), __uint_as_float(d0[c4 * 4 + 1]),
            __uint_as_float(d0[c4 * 4 + 2]), __uint_as_float(d0[c4 * 4 + 3]));
        *reinterpret_cast<float4*>(drow + 32 + c4 * 4) = make_float4(
            __uint_as_float(d1[c4 * 4 + 0]), __uint_as_float(d1[c4 * 4 + 1]),
            __uint_as_float(d1[c4 * 4 + 2]), __uint_as_float(d1[c4 * 4 + 3]));
    }
    __syncthreads();
#else
    // ---------------- SIMT fallback (base-arch pass only) -----------------
    (void)sb; (void)tmem; (void)mctr;
    float acc[64];
    #pragma unroll
    for (int j = 0; j < 64; j++) acc[j] = 0.f;
    for (int c0 = 0; c0 < K; c0 += 128) {
        const int kch = (K - c0 < 128) ? (K - c0) : 128;
        const int K4 = kch >> 2;
        for (int i = tid; i < 64 * K4; i += 128) {
            int r = i / K4, c4 = i % K4;
            *reinterpret_cast<float4*>(smf + r * 128 + c4 * 4) =
                *reinterpret_cast<const float4*>(Bsrc + (size_t)r * ldb + c0 + c4 * 4);
        }
        __syncthreads();
        const float* arow = Asrc + (size_t)tid * lda + c0;
        for (int c4 = 0; c4 < K4; c4++) {
            float4 a4 = *reinterpret_cast<const float4*>(arow + c4 * 4);
            #pragma unroll
            for (int j = 0; j < 64; j++) {
                const float* br = smf + j * 128 + c4 * 4;
                acc[j] += a4.x * br[0] + a4.y * br[1] + a4.z * br[2] + a4.w * br[3];
            }
        }
        __syncthreads();
    }
    float* drow = dst + (size_t)tid * ldd;
    #pragma unroll
    for (int j = 0; j < 64; j += 4)
        *reinterpret_cast<float4*>(drow + j) =
            make_float4(acc[j], acc[j + 1], acc[j + 2], acc[j + 3]);
    __syncthreads();
#endif
}

// ---------------------------------------------------------------------------
__global__ void __launch_bounds__(128, 1) k_rnn(
    const float* __restrict__ Wih1, const float* __restrict__ bih1,
    const float* __restrict__ Whh1, const float* __restrict__ bhh1,
    const float* __restrict__ Wih2, const float* __restrict__ bih2,
    const float* __restrict__ Whh2, const float* __restrict__ bhh2,
    const float* __restrict__ Wg,   const float* __restrict__ bg,
    const float* __restrict__ Wo1,  const float* __restrict__ bo1,
    const float* __restrict__ Wo2,  const float* __restrict__ bo2,
    float* __restrict__ out)
{
    extern __shared__ char dynsm[];
    const uint32_t sb = cvta_s(dynsm);
    float* smf = reinterpret_cast<float*>(dynsm);
    const int tid = threadIdx.x;
    const int u = blockIdx.x;
    unsigned target = 0;
    uint32_t mctr = 0;
    uint32_t tmem = 0;

#if HAS_TCGEN05
    if (tid < 32) {
        asm volatile(
            "tcgen05.alloc.cta_group::1.sync.aligned.shared::cta.b32 [%0], %1;"
            :: "r"(sb), "r"(64u) : "memory");
        asm volatile("tcgen05.relinquish_alloc_permit.cta_group::1.sync.aligned;");
    }
    if (tid == 0) {
        asm volatile("mbarrier.init.shared.b64 [%0], 1;" :: "r"(sb + 8) : "memory");
    }
    __syncthreads();
    asm volatile("ld.shared.b32 %0, [%1];" : "=r"(tmem) : "r"(sb));
#endif

    const int n4 = BB * HH / 4;   // 32768 float4

    for (int t = 0; t < TT; t++) {
        // ================= phase A: h1pre = x_t@Wih1^T + h1@Whh1^T ========
        if (u < 144) {
            int jt = u / 9, s = u - jt * 9;
            int j0 = jt * 64;
            float* dst = partA + (size_t)s * (BB * HH) + j0;
            if (s == 0)
                run_unit(bufX + (size_t)t * BB * II, II,
                         Wih1 + (size_t)j0 * II, II,
                         64, sb, smf, tmem, dst, HH, tid, mctr);
            else
                run_unit(bufH1 + (s - 1) * 128, HH,
                         Whh1 + (size_t)j0 * HH + (s - 1) * 128, HH,
                         128, sb, smf, tmem, dst, HH, tid, mctr);
        }
        gsync(target);
        // ---- reduce A: h1 = tanh(sum9 + biases) ----
        for (int i4 = u * 128 + tid; i4 < n4; i4 += NCTA * 128) {
            int j0 = (i4 << 2) & (HH - 1);
            float4 b1 = *reinterpret_cast<const float4*>(bih1 + j0);
            float4 b2 = *reinterpret_cast<const float4*>(bhh1 + j0);
            float4 s = make_float4(b1.x + b2.x, b1.y + b2.y, b1.z + b2.z, b1.w + b2.w);
            #pragma unroll
            for (int ss = 0; ss < 9; ss++) {
                float4 p = reinterpret_cast<const float4*>(partA)[ss * n4 + i4];
                s.x += p.x; s.y += p.y; s.z += p.z; s.w += p.w;
            }
            reinterpret_cast<float4*>(bufH1)[i4] =
                make_float4(tanhf(s.x), tanhf(s.y), tanhf(s.z), tanhf(s.w));
        }
        gsync(target);
        // ================= phase B: h2pre = h1@Wih2^T + h2@Whh2^T =========
        if (u < 128) {
            int jt = u >> 3, s = u & 7;
            int j0 = jt * 64;
            const float* A  = (s < 4) ? bufH1 + s * 256 : bufH2 + (s - 4) * 256;
            const float* Bw = (s < 4) ? Wih2 + (size_t)j0 * HH + s * 256
                                      : Whh2 + (size_t)j0 * HH + (s - 4) * 256;
            run_unit(A, HH, Bw, HH, 256, sb, smf, tmem,
                     partA + (size_t)s * (BB * HH) + j0, HH, tid, mctr);
        }
        gsync(target);
        // ---- reduce B: h2 = u*tanh(sum8+b) + (1-u)*h2 ----
        for (int i4 = u * 128 + tid; i4 < n4; i4 += NCTA * 128) {
            int j0 = (i4 << 2) & (HH - 1);
            float4 b1 = *reinterpret_cast<const float4*>(bih2 + j0);
            float4 b2 = *reinterpret_cast<const float4*>(bhh2 + j0);
            float4 s = make_float4(b1.x + b2.x, b1.y + b2.y, b1.z + b2.z, b1.w + b2.w);
            #pragma unroll
            for (int ss = 0; ss < 8; ss++) {
                float4 p = reinterpret_cast<const float4*>(partA)[ss * n4 + i4];
                s.x += p.x; s.y += p.y; s.z += p.z; s.w += p.w;
            }
            float4 uu = reinterpret_cast<const float4*>(g_u)[i4];
            float4 hp = reinterpret_cast<const float4*>(bufH2)[i4];
            float4 r;
            r.x = uu.x * tanhf(s.x) + (1.f - uu.x) * hp.x;
            r.y = uu.y * tanhf(s.y) + (1.f - uu.y) * hp.y;
            r.z = uu.z * tanhf(s.z) + (1.f - uu.z) * hp.z;
            r.w = uu.w * tanhf(s.w) + (1.f - uu.w) * hp.w;
            reinterpret_cast<float4*>(bufH2)[i4] = r;
        }
        gsync(target);
        // ====== phase C: gate (128 units) + output heads (8 units) ========
        if (u < 128) {
            int jt = u >> 3, s = u & 7;
            int j0 = jt * 64;
            const float* A = (s < 4) ? bufH1 + s * 256 : bufH2 + (s - 4) * 256;
            run_unit(A, HH, Wg + (size_t)j0 * 2048 + s * 256, 2048,
                     256, sb, smf, tmem,
                     partA + (size_t)s * (BB * HH) + j0, HH, tid, mctr);
        } else if (u < 136) {
            int i = u - 128;
            int head = i >> 2, s = i & 3;
            const float* A  = (head ? bufH2 : bufH1) + s * 256;
            const float* Bw = (head ? Wo2 : Wo1) + s * 256;
            run_unit(A, HH, Bw, HH, 256, sb, smf, tmem,
                     partH + (size_t)s * (BB * 128) + head * 64, 128, tid, mctr);
        }
        gsync(target);
        // ---- reduce C: u = sigmoid(sum8+bg); out = tanh+tanh ----
        for (int i4 = u * 128 + tid; i4 < n4; i4 += NCTA * 128) {
            int j0 = (i4 << 2) & (HH - 1);
            float4 bG = *reinterpret_cast<const float4*>(bg + j0);
            float4 s = bG;
            #pragma unroll
            for (int ss = 0; ss < 8; ss++) {
                float4 p = reinterpret_cast<const float4*>(partA)[ss * n4 + i4];
                s.x += p.x; s.y += p.y; s.z += p.z; s.w += p.w;
            }
            float4 r;
            r.x = 1.f / (1.f + expf(-s.x));
            r.y = 1.f / (1.f + expf(-s.y));
            r.z = 1.f / (1.f + expf(-s.z));
            r.w = 1.f / (1.f + expf(-s.w));
            reinterpret_cast<float4*>(g_u)[i4] = r;
        }
        for (int i = u * 128 + tid; i < BB * OO; i += NCTA * 128) {
            int b = i >> 6, o = i & 63;
            float s1 = bo1[o], s2 = bo2[o];
            #pragma unroll
            for (int ss = 0; ss < 4; ss++) {
                s1 += partH[ss * (BB * 128) + b * 128 + o];
                s2 += partH[ss * (BB * 128) + b * 128 + o + 64];
            }
            out[((size_t)b * TT + t) * OO + o] = tanhf(s1) + tanhf(s2);
        }
        gsync(target);
    }

    __syncthreads();
#if HAS_TCGEN05
    if (tid < 32) {
        asm volatile("tcgen05.dealloc.cta_group::1.sync.aligned.b32 %0, %1;"
                     :: "r"(tmem), "r"(64u));
    }
#endif
}

// ---------------------------------------------------------------------------
extern "C" void kernel_launch(void* const* d_in, const int* in_sizes, int n_in,
                              void* d_out, int out_size) {
    const float* x    = (const float*)d_in[0];
    const float* Wih1 = (const float*)d_in[1];
    const float* bih1 = (const float*)d_in[2];
    const float* Whh1 = (const float*)d_in[3];
    const float* bhh1 = (const float*)d_in[4];
    const float* Wih2 = (const float*)d_in[5];
    const float* bih2 = (const float*)d_in[6];
    const float* Whh2 = (const float*)d_in[7];
    const float* bhh2 = (const float*)d_in[8];
    const float* Wg   = (const float*)d_in[9];
    const float* bg   = (const float*)d_in[10];
    const float* Wo1  = (const float*)d_in[11];
    const float* bo1  = (const float*)d_in[12];
    const float* Wo2  = (const float*)d_in[13];
    const float* bo2  = (const float*)d_in[14];
    float* out = (float*)d_out;

    cudaFuncSetAttribute(k_rnn, cudaFuncAttributeMaxDynamicSharedMemorySize,
                         SMEM_BYTES);

    k_init<<<(BB * HH + 255) / 256, 256>>>();
    k_prepx<<<(TT * BB * II + 255) / 256, 256>>>(x);
    k_rnn<<<NCTA, 128, SMEM_BYTES>>>(Wih1, bih1, Whh1, bhh1,
                                     Wih2, bih2, Whh2, bhh2,
                                     Wg, bg, Wo1, bo1, Wo2, bo2, out);
}